// round 1
// baseline (speedup 1.0000x reference)
#include <cuda_runtime.h>
#include <math.h>

#define H   128
#define H2  256
#define H3  384
#define WMC 257          // W_msg columns = 2H+1

#define MAXN 50000
#define MAXE 800000
#define MAXT 4

// ---------------- scratch (static device globals; no allocation) ----------------
__device__ float g_S  [(size_t)MAXN * H];    // sum of hv[src] into dst
__device__ float g_X  [(size_t)MAXN * H2];   // [deg*hv, S]
__device__ float g_gi [(size_t)MAXN * H3];
__device__ float g_gh [(size_t)MAXN * H3];
__device__ float g_h0 [(size_t)MAXN * H];
__device__ float g_h1 [(size_t)MAXN * H];
__device__ float g_deg[MAXN];
__device__ float g_se [MAXN];
__device__ float g_Wc [(size_t)MAXT * H3 * H2];  // W_ih @ W_msg[:, :2H]
__device__ float g_u1 [MAXT * H3];               // W_ih @ w_e
__device__ float g_u2 [MAXT * H3];               // W_ih @ b_msg

// ---------------- utility ----------------
__global__ void zero_kernel(float* __restrict__ p, size_t n) {
    size_t i = (size_t)blockIdx.x * blockDim.x + threadIdx.x;
    size_t stride = (size_t)gridDim.x * blockDim.x;
    for (; i < n; i += stride) p[i] = 0.f;
}

// ---------------- per-graph aggregates (round-invariant) ----------------
__global__ void degse_kernel(const int* __restrict__ dst, const float* __restrict__ he, int E) {
    int e = blockIdx.x * blockDim.x + threadIdx.x;
    if (e >= E) return;
    int d = dst[e];
    atomicAdd(&g_deg[d], 1.0f);
    atomicAdd(&g_se[d], he[e]);
}

// ---------------- weight folding ----------------
// Wc[t][j][k] = sum_i W_ih[t][j][i] * W_msg[t][i][k],  k < 2H
__global__ void fold_wc_kernel(const float* __restrict__ W_ih, const float* __restrict__ W_msg, int T) {
    long idx = (long)blockIdx.x * blockDim.x + threadIdx.x;
    if (idx >= (long)T * H3 * H2) return;
    int k = (int)(idx % H2);
    int j = (int)((idx / H2) % H3);
    int t = (int)(idx / ((long)H2 * H3));
    const float* wi = W_ih + ((size_t)t * H3 + j) * H2;
    const float* wm = W_msg + (size_t)t * H2 * WMC + k;
    float acc = 0.f;
    #pragma unroll 4
    for (int i = 0; i < H2; i++) acc += wi[i] * wm[(size_t)i * WMC];
    g_Wc[idx] = acc;
}

// u1[t][j] = sum_i W_ih[t][j][i] * W_msg[t][i][2H];  u2[t][j] = sum_i W_ih[t][j][i] * b_msg[t][i]
__global__ void fold_u_kernel(const float* __restrict__ W_ih, const float* __restrict__ W_msg,
                              const float* __restrict__ b_msg, int T) {
    int idx = blockIdx.x * blockDim.x + threadIdx.x;
    if (idx >= T * H3) return;
    int j = idx % H3, t = idx / H3;
    const float* wi = W_ih + ((size_t)t * H3 + j) * H2;
    const float* wm = W_msg + (size_t)t * H2 * WMC;
    const float* bm = b_msg + (size_t)t * H2;
    float a1 = 0.f, a2 = 0.f;
    for (int i = 0; i < H2; i++) {
        float w = wi[i];
        a1 += w * wm[(size_t)i * WMC + H2];
        a2 += w * bm[i];
    }
    g_u1[idx] = a1;
    g_u2[idx] = a2;
}

// ---------------- edge scatter: S[dst] += hv[src] (one warp per edge) ----------------
__global__ void scatter_kernel(const float* __restrict__ hv, const int* __restrict__ src,
                               const int* __restrict__ dst, int E) {
    int w = (blockIdx.x * blockDim.x + threadIdx.x) >> 5;
    int lane = threadIdx.x & 31;
    if (w >= E) return;
    int s = __ldg(src + w);
    int d = __ldg(dst + w);
    float4 v = *(((const float4*)(hv + (size_t)s * H)) + lane);
    float4* p = ((float4*)(g_S + (size_t)d * H)) + lane;
    asm volatile("red.global.add.v4.f32 [%0], {%1,%2,%3,%4};"
                 :: "l"(p), "f"(v.x), "f"(v.y), "f"(v.z), "f"(v.w) : "memory");
}

// ---------------- X = [deg*hv, S] ----------------
__global__ void xmat_kernel(const float* __restrict__ hv, int N) {
    int idx = blockIdx.x * blockDim.x + threadIdx.x;  // n*64 + q (float4 over 256)
    if (idx >= N * 64) return;
    int n = idx >> 6, q = idx & 63;
    float4 v;
    if (q < 32) {
        v = ((const float4*)(hv + (size_t)n * H))[q];
        float d = g_deg[n];
        v.x *= d; v.y *= d; v.z *= d; v.w *= d;
    } else {
        v = ((const float4*)(g_S + (size_t)n * H))[q - 32];
    }
    ((float4*)(g_X + (size_t)n * H2))[q] = v;
}

// ---------------- SGEMM (NT): C[M,Nout] = A[M,K] @ B[Nout,K]^T ----------------
// 128x128 block tile, BK=8, 256 threads, 8x8 per-thread microtile.
__global__ __launch_bounds__(256) void sgemm_nt_kernel(
    const float* __restrict__ A, const float* __restrict__ B, float* __restrict__ C,
    int M, int Nout, int K)
{
    __shared__ float As[8][128];
    __shared__ float Bs[8][128];
    int bm = blockIdx.x, bn = blockIdx.y;
    int tid = threadIdx.x;
    int tx = tid & 15, ty = tid >> 4;

    float acc[8][8];
    #pragma unroll
    for (int i = 0; i < 8; i++)
        #pragma unroll
        for (int j = 0; j < 8; j++) acc[i][j] = 0.f;

    int loadRow = tid >> 1;
    int loadK4  = (tid & 1) * 4;
    int aRow = bm * 128 + loadRow;
    int bRow = bn * 128 + loadRow;

    for (int k0 = 0; k0 < K; k0 += 8) {
        float4 av = make_float4(0.f, 0.f, 0.f, 0.f);
        if (aRow < M) av = *(const float4*)(A + (size_t)aRow * K + k0 + loadK4);
        float4 bv = make_float4(0.f, 0.f, 0.f, 0.f);
        if (bRow < Nout) bv = *(const float4*)(B + (size_t)bRow * K + k0 + loadK4);

        __syncthreads();
        As[loadK4 + 0][loadRow] = av.x;
        As[loadK4 + 1][loadRow] = av.y;
        As[loadK4 + 2][loadRow] = av.z;
        As[loadK4 + 3][loadRow] = av.w;
        Bs[loadK4 + 0][loadRow] = bv.x;
        Bs[loadK4 + 1][loadRow] = bv.y;
        Bs[loadK4 + 2][loadRow] = bv.z;
        Bs[loadK4 + 3][loadRow] = bv.w;
        __syncthreads();

        #pragma unroll
        for (int kk = 0; kk < 8; kk++) {
            float4 a0 = *(const float4*)&As[kk][ty * 8];
            float4 a1 = *(const float4*)&As[kk][ty * 8 + 4];
            float4 b0 = *(const float4*)&Bs[kk][tx * 8];
            float4 b1 = *(const float4*)&Bs[kk][tx * 8 + 4];
            float av_[8] = {a0.x, a0.y, a0.z, a0.w, a1.x, a1.y, a1.z, a1.w};
            float bv_[8] = {b0.x, b0.y, b0.z, b0.w, b1.x, b1.y, b1.z, b1.w};
            #pragma unroll
            for (int i = 0; i < 8; i++)
                #pragma unroll
                for (int j = 0; j < 8; j++)
                    acc[i][j] = fmaf(av_[i], bv_[j], acc[i][j]);
        }
    }

    #pragma unroll
    for (int i = 0; i < 8; i++) {
        int m = bm * 128 + ty * 8 + i;
        if (m < M) {
            float* cp = C + (size_t)m * Nout + bn * 128 + tx * 8;
            *(float4*)(cp)     = make_float4(acc[i][0], acc[i][1], acc[i][2], acc[i][3]);
            *(float4*)(cp + 4) = make_float4(acc[i][4], acc[i][5], acc[i][6], acc[i][7]);
        }
    }
}

// ---------------- fused GRU elementwise ----------------
__global__ void gru_kernel(const float* __restrict__ hv,
                           const float* __restrict__ b_ih, const float* __restrict__ b_hh,
                           const float* __restrict__ u1, const float* __restrict__ u2,
                           float* __restrict__ out, int N)
{
    int idx = blockIdx.x * blockDim.x + threadIdx.x;
    if (idx >= N * H) return;
    int n = idx >> 7, c = idx & 127;
    float d = g_deg[n], s = g_se[n];
    size_t b = (size_t)n * H3;

    float ir = g_gi[b + c]         + s * u1[c]         + d * u2[c]         + b_ih[c];
    float iz = g_gi[b + H + c]     + s * u1[H + c]     + d * u2[H + c]     + b_ih[H + c];
    float in_ = g_gi[b + 2*H + c]  + s * u1[2*H + c]   + d * u2[2*H + c]   + b_ih[2*H + c];
    float hr = g_gh[b + c]         + b_hh[c];
    float hz = g_gh[b + H + c]     + b_hh[H + c];
    float hn = g_gh[b + 2*H + c]   + b_hh[2*H + c];

    float r = 1.f / (1.f + expf(-(ir + hr)));
    float z = 1.f / (1.f + expf(-(iz + hz)));
    float nn = tanhf(in_ + r * hn);
    float h  = hv[(size_t)n * H + c];
    out[(size_t)n * H + c] = (1.f - z) * nn + z * h;
}

// ---------------- launch ----------------
extern "C" void kernel_launch(void* const* d_in, const int* in_sizes, int n_in,
                              void* d_out, int out_size)
{
    const float* hv0   = (const float*)d_in[0];
    const float* he    = (const float*)d_in[1];
    const int*   src   = (const int*)d_in[2];
    const int*   dst   = (const int*)d_in[3];
    const float* W_msg = (const float*)d_in[4];
    const float* b_msg = (const float*)d_in[5];
    const float* W_ih  = (const float*)d_in[6];
    const float* W_hh  = (const float*)d_in[7];
    const float* b_ih  = (const float*)d_in[8];
    const float* b_hh  = (const float*)d_in[9];

    int N = in_sizes[0] / H;
    int E = in_sizes[2];
    int T = in_sizes[8] / H3;
    if (T > MAXT) T = MAXT;

    float *pS, *pX, *pgi, *pgh, *ph0, *ph1, *pdeg, *pse, *pWc, *pu1, *pu2;
    cudaGetSymbolAddress((void**)&pS,  g_S);
    cudaGetSymbolAddress((void**)&pX,  g_X);
    cudaGetSymbolAddress((void**)&pgi, g_gi);
    cudaGetSymbolAddress((void**)&pgh, g_gh);
    cudaGetSymbolAddress((void**)&ph0, g_h0);
    cudaGetSymbolAddress((void**)&ph1, g_h1);
    cudaGetSymbolAddress((void**)&pdeg, g_deg);
    cudaGetSymbolAddress((void**)&pse,  g_se);
    cudaGetSymbolAddress((void**)&pWc,  g_Wc);
    cudaGetSymbolAddress((void**)&pu1,  g_u1);
    cudaGetSymbolAddress((void**)&pu2,  g_u2);

    // zero deg/se, then aggregate
    zero_kernel<<<256, 256>>>(pdeg, (size_t)N);
    zero_kernel<<<256, 256>>>(pse,  (size_t)N);
    degse_kernel<<<(E + 255) / 256, 256>>>(dst, he, E);

    // weight folds
    long wc_total = (long)T * H3 * H2;
    fold_wc_kernel<<<(int)((wc_total + 255) / 256), 256>>>(W_ih, W_msg, T);
    fold_u_kernel<<<(T * H3 + 255) / 256, 256>>>(W_ih, W_msg, b_msg, T);

    const float* cur = hv0;
    for (int t = 0; t < T; t++) {
        zero_kernel<<<1024, 256>>>(pS, (size_t)N * H);
        scatter_kernel<<<(E * 8 + 63) / 64, 256>>>(cur, src, dst, E);
        xmat_kernel<<<(N * 64 + 255) / 256, 256>>>(cur, N);

        dim3 g1((N + 127) / 128, H3 / 128);
        sgemm_nt_kernel<<<g1, 256>>>(pX, pWc + (size_t)t * H3 * H2, pgi, N, H3, H2);
        sgemm_nt_kernel<<<g1, 256>>>(cur, W_hh + (size_t)t * H3 * H, pgh, N, H3, H);

        float* outp = (t == T - 1) ? (float*)d_out : ((t & 1) ? ph1 : ph0);
        gru_kernel<<<(N * H + 255) / 256, 256>>>(cur, b_ih + (size_t)t * H3, b_hh + (size_t)t * H3,
                                                 pu1 + (size_t)t * H3, pu2 + (size_t)t * H3,
                                                 outp, N);
        cur = outp;
    }
}

// round 3
// speedup vs baseline: 1.1793x; 1.1793x over previous
#include <cuda_runtime.h>
#include <math.h>

#define H   128
#define H2  256
#define H3  384
#define WMC 257          // W_msg columns = 2H+1

#define MAXN 50000
#define MAXE 800000
#define MAXT 4

// ---------------- scratch (static device globals; no allocation) ----------------
__device__ float g_S  [(size_t)MAXN * H];    // sum of hv[src] into dst
__device__ float g_X  [(size_t)MAXN * H2];   // [deg*hv, S]
__device__ float g_gi [(size_t)MAXN * H3];
__device__ float g_gh [(size_t)MAXN * H3];
__device__ float g_h0 [(size_t)MAXN * H];
__device__ float g_h1 [(size_t)MAXN * H];
__device__ float g_deg[MAXN];
__device__ float g_se [MAXN];
__device__ float g_Wc [(size_t)MAXT * H3 * H2];  // W_ih @ W_msg[:, :2H]
__device__ float g_u1 [MAXT * H3];               // W_ih @ w_e
__device__ float g_u2 [MAXT * H3];               // W_ih @ b_msg

// ---------------- utility ----------------
__global__ void zero_kernel(float* __restrict__ p, size_t n) {
    size_t i = (size_t)blockIdx.x * blockDim.x + threadIdx.x;
    size_t stride = (size_t)gridDim.x * blockDim.x;
    for (; i < n; i += stride) p[i] = 0.f;
}

// ---------------- per-graph aggregates (round-invariant) ----------------
__global__ void degse_kernel(const int* __restrict__ dst, const float* __restrict__ he, int E) {
    int e = blockIdx.x * blockDim.x + threadIdx.x;
    if (e >= E) return;
    int d = dst[e];
    atomicAdd(&g_deg[d], 1.0f);
    atomicAdd(&g_se[d], he[e]);
}

// ---------------- weight folding ----------------
__global__ void fold_wc_kernel(const float* __restrict__ W_ih, const float* __restrict__ W_msg, int T) {
    long idx = (long)blockIdx.x * blockDim.x + threadIdx.x;
    if (idx >= (long)T * H3 * H2) return;
    int k = (int)(idx % H2);
    int j = (int)((idx / H2) % H3);
    int t = (int)(idx / ((long)H2 * H3));
    const float* wi = W_ih + ((size_t)t * H3 + j) * H2;
    const float* wm = W_msg + (size_t)t * H2 * WMC + k;
    float acc = 0.f;
    #pragma unroll 4
    for (int i = 0; i < H2; i++) acc += wi[i] * wm[(size_t)i * WMC];
    g_Wc[idx] = acc;
}

__global__ void fold_u_kernel(const float* __restrict__ W_ih, const float* __restrict__ W_msg,
                              const float* __restrict__ b_msg, int T) {
    int idx = blockIdx.x * blockDim.x + threadIdx.x;
    if (idx >= T * H3) return;
    int j = idx % H3, t = idx / H3;
    const float* wi = W_ih + ((size_t)t * H3 + j) * H2;
    const float* wm = W_msg + (size_t)t * H2 * WMC;
    const float* bm = b_msg + (size_t)t * H2;
    float a1 = 0.f, a2 = 0.f;
    for (int i = 0; i < H2; i++) {
        float w = wi[i];
        a1 += w * wm[(size_t)i * WMC + H2];
        a2 += w * bm[i];
    }
    g_u1[idx] = a1;
    g_u2[idx] = a2;
}

// ---------------- edge scatter: S[dst] += hv[src] (one warp per edge) ----------------
__global__ void scatter_kernel(const float* __restrict__ hv, const int* __restrict__ src,
                               const int* __restrict__ dst, int E) {
    int w = (blockIdx.x * blockDim.x + threadIdx.x) >> 5;
    int lane = threadIdx.x & 31;
    if (w >= E) return;
    int s = __ldg(src + w);
    int d = __ldg(dst + w);
    float4 v = *(((const float4*)(hv + (size_t)s * H)) + lane);
    float4* p = ((float4*)(g_S + (size_t)d * H)) + lane;
    asm volatile("red.global.add.v4.f32 [%0], {%1,%2,%3,%4};"
                 :: "l"(p), "f"(v.x), "f"(v.y), "f"(v.z), "f"(v.w) : "memory");
}

// ---------------- X = [deg*hv, S] ----------------
__global__ void xmat_kernel(const float* __restrict__ hv, int N) {
    int idx = blockIdx.x * blockDim.x + threadIdx.x;  // n*64 + q (float4 over 256)
    if (idx >= N * 64) return;
    int n = idx >> 6, q = idx & 63;
    float4 v;
    if (q < 32) {
        v = ((const float4*)(hv + (size_t)n * H))[q];
        float d = g_deg[n];
        v.x *= d; v.y *= d; v.z *= d; v.w *= d;
    } else {
        v = ((const float4*)(g_S + (size_t)n * H))[q - 32];
    }
    ((float4*)(g_X + (size_t)n * H2))[q] = v;
}

// ---------------- 3xTF32 tensor-core GEMM (NT): C = A @ B^T, fp32-accurate ---------
// 128x128 block tile, BK=16, 256 threads (8 warps, 2x4), warp tile 64x32.
// Each operand split hi/lo; three mma.sync.m16n8k8 per fragment pair:
//   hi*hi + lo*hi + hi*lo  (error ~2^-21, fp32-like)
#define SMS 136

__device__ __forceinline__ unsigned f2tf32(float f) {
    unsigned r;
    asm("cvt.rna.tf32.f32 %0, %1;" : "=r"(r) : "f"(f));
    return r;
}

__device__ __forceinline__ void split_tf32(float f, unsigned& hi, unsigned& lo) {
    hi = f2tf32(f);
    float r = f - __uint_as_float(hi);
    lo = f2tf32(r);
}

__device__ __forceinline__ void mma_tf32(float* acc, const unsigned* a, const unsigned* b) {
    asm volatile(
        "mma.sync.aligned.m16n8k8.row.col.f32.tf32.tf32.f32 "
        "{%0,%1,%2,%3}, {%4,%5,%6,%7}, {%8,%9}, {%0,%1,%2,%3};"
        : "+f"(acc[0]), "+f"(acc[1]), "+f"(acc[2]), "+f"(acc[3])
        : "r"(a[0]), "r"(a[1]), "r"(a[2]), "r"(a[3]), "r"(b[0]), "r"(b[1]));
}

__global__ __launch_bounds__(256) void mma_tf32x3_nt(
    const float* __restrict__ A, const float* __restrict__ B, float* __restrict__ C,
    int M, int Nout, int K)
{
    __shared__ unsigned AsH[16 * SMS];
    __shared__ unsigned AsL[16 * SMS];
    __shared__ unsigned BsH[16 * SMS];
    __shared__ unsigned BsL[16 * SMS];

    int bm = blockIdx.x, bn = blockIdx.y;
    int tid = threadIdx.x;
    int lane = tid & 31;
    int warp = tid >> 5;
    int wm = warp >> 2;        // 0..1
    int wn = warp & 3;         // 0..3
    int mb = wm * 64;
    int nb = wn * 32;
    int qk = lane & 3;
    int qm = lane >> 2;

    int lrow   = tid >> 1;            // 0..127
    int lkhalf = (tid & 1) * 8;       // 0 or 8
    int aRow = bm * 128 + lrow;
    int bRow = bn * 128 + lrow;
    bool aOk = aRow < M;
    bool bOk = bRow < Nout;

    float acc[4][4][4];
    #pragma unroll
    for (int i = 0; i < 4; i++)
        #pragma unroll
        for (int j = 0; j < 4; j++)
            #pragma unroll
            for (int c = 0; c < 4; c++) acc[i][j][c] = 0.f;

    for (int k0 = 0; k0 < K; k0 += 16) {
        float a[8] = {0,0,0,0,0,0,0,0};
        float b[8] = {0,0,0,0,0,0,0,0};
        if (aOk) {
            const float* ap = A + (size_t)aRow * K + k0 + lkhalf;
            float4 v0 = *(const float4*)ap;
            float4 v1 = *(const float4*)(ap + 4);
            a[0]=v0.x; a[1]=v0.y; a[2]=v0.z; a[3]=v0.w;
            a[4]=v1.x; a[5]=v1.y; a[6]=v1.z; a[7]=v1.w;
        }
        if (bOk) {
            const float* bp = B + (size_t)bRow * K + k0 + lkhalf;
            float4 v0 = *(const float4*)bp;
            float4 v1 = *(const float4*)(bp + 4);
            b[0]=v0.x; b[1]=v0.y; b[2]=v0.z; b[3]=v0.w;
            b[4]=v1.x; b[5]=v1.y; b[6]=v1.z; b[7]=v1.w;
        }
        __syncthreads();
        #pragma unroll
        for (int q = 0; q < 8; q++) {
            unsigned hi, lo;
            split_tf32(a[q], hi, lo);
            AsH[(lkhalf + q) * SMS + lrow] = hi;
            AsL[(lkhalf + q) * SMS + lrow] = lo;
            split_tf32(b[q], hi, lo);
            BsH[(lkhalf + q) * SMS + lrow] = hi;
            BsL[(lkhalf + q) * SMS + lrow] = lo;
        }
        __syncthreads();

        #pragma unroll
        for (int s = 0; s < 2; s++) {
            int k8 = s * 8;
            unsigned afH[4][4], afL[4][4];
            #pragma unroll
            for (int i = 0; i < 4; i++) {
                int mrow = mb + i * 16 + qm;
                int o0 = (k8 + qk) * SMS + mrow;
                int o1 = (k8 + qk + 4) * SMS + mrow;
                afH[i][0] = AsH[o0];     afL[i][0] = AsL[o0];
                afH[i][1] = AsH[o0 + 8]; afL[i][1] = AsL[o0 + 8];
                afH[i][2] = AsH[o1];     afL[i][2] = AsL[o1];
                afH[i][3] = AsH[o1 + 8]; afL[i][3] = AsL[o1 + 8];
            }
            unsigned bfH[4][2], bfL[4][2];
            #pragma unroll
            for (int j = 0; j < 4; j++) {
                int ncol = nb + j * 8 + qm;
                bfH[j][0] = BsH[(k8 + qk) * SMS + ncol];
                bfH[j][1] = BsH[(k8 + qk + 4) * SMS + ncol];
                bfL[j][0] = BsL[(k8 + qk) * SMS + ncol];
                bfL[j][1] = BsL[(k8 + qk + 4) * SMS + ncol];
            }
            #pragma unroll
            for (int i = 0; i < 4; i++)
                #pragma unroll
                for (int j = 0; j < 4; j++) {
                    mma_tf32(acc[i][j], afL[i], bfH[j]);   // lo*hi
                    mma_tf32(acc[i][j], afH[i], bfL[j]);   // hi*lo
                    mma_tf32(acc[i][j], afH[i], bfH[j]);   // hi*hi (last: largest term)
                }
        }
    }

    #pragma unroll
    for (int i = 0; i < 4; i++) {
        int r0 = bm * 128 + mb + i * 16 + qm;
        int r1 = r0 + 8;
        #pragma unroll
        for (int j = 0; j < 4; j++) {
            int col = bn * 128 + nb + j * 8 + (lane & 3) * 2;
            if (r0 < M)
                *(float2*)(C + (size_t)r0 * Nout + col) = make_float2(acc[i][j][0], acc[i][j][1]);
            if (r1 < M)
                *(float2*)(C + (size_t)r1 * Nout + col) = make_float2(acc[i][j][2], acc[i][j][3]);
        }
    }
}

// ---------------- fused GRU elementwise ----------------
__global__ void gru_kernel(const float* __restrict__ hv,
                           const float* __restrict__ b_ih, const float* __restrict__ b_hh,
                           const float* __restrict__ u1, const float* __restrict__ u2,
                           float* __restrict__ out, int N)
{
    int idx = blockIdx.x * blockDim.x + threadIdx.x;
    if (idx >= N * H) return;
    int n = idx >> 7, c = idx & 127;
    float d = g_deg[n], s = g_se[n];
    size_t b = (size_t)n * H3;

    float ir = g_gi[b + c]         + s * u1[c]         + d * u2[c]         + b_ih[c];
    float iz = g_gi[b + H + c]     + s * u1[H + c]     + d * u2[H + c]     + b_ih[H + c];
    float in_ = g_gi[b + 2*H + c]  + s * u1[2*H + c]   + d * u2[2*H + c]   + b_ih[2*H + c];
    float hr = g_gh[b + c]         + b_hh[c];
    float hz = g_gh[b + H + c]     + b_hh[H + c];
    float hn = g_gh[b + 2*H + c]   + b_hh[2*H + c];

    float r = 1.f / (1.f + expf(-(ir + hr)));
    float z = 1.f / (1.f + expf(-(iz + hz)));
    float nn = tanhf(in_ + r * hn);
    float h  = hv[(size_t)n * H + c];
    out[(size_t)n * H + c] = (1.f - z) * nn + z * h;
}

// ---------------- launch ----------------
extern "C" void kernel_launch(void* const* d_in, const int* in_sizes, int n_in,
                              void* d_out, int out_size)
{
    const float* hv0   = (const float*)d_in[0];
    const float* he    = (const float*)d_in[1];
    const int*   src   = (const int*)d_in[2];
    const int*   dst   = (const int*)d_in[3];
    const float* W_msg = (const float*)d_in[4];
    const float* b_msg = (const float*)d_in[5];
    const float* W_ih  = (const float*)d_in[6];
    const float* W_hh  = (const float*)d_in[7];
    const float* b_ih  = (const float*)d_in[8];
    const float* b_hh  = (const float*)d_in[9];

    int N = in_sizes[0] / H;
    int E = in_sizes[2];
    int T = in_sizes[8] / H3;
    if (T > MAXT) T = MAXT;

    float *pS, *pX, *pgi, *pgh, *ph0, *ph1, *pdeg, *pse, *pWc, *pu1, *pu2;
    cudaGetSymbolAddress((void**)&pS,  g_S);
    cudaGetSymbolAddress((void**)&pX,  g_X);
    cudaGetSymbolAddress((void**)&pgi, g_gi);
    cudaGetSymbolAddress((void**)&pgh, g_gh);
    cudaGetSymbolAddress((void**)&ph0, g_h0);
    cudaGetSymbolAddress((void**)&ph1, g_h1);
    cudaGetSymbolAddress((void**)&pdeg, g_deg);
    cudaGetSymbolAddress((void**)&pse,  g_se);
    cudaGetSymbolAddress((void**)&pWc,  g_Wc);
    cudaGetSymbolAddress((void**)&pu1,  g_u1);
    cudaGetSymbolAddress((void**)&pu2,  g_u2);

    // zero deg/se, then aggregate
    zero_kernel<<<256, 256>>>(pdeg, (size_t)N);
    zero_kernel<<<256, 256>>>(pse,  (size_t)N);
    degse_kernel<<<(E + 255) / 256, 256>>>(dst, he, E);

    // weight folds
    long wc_total = (long)T * H3 * H2;
    fold_wc_kernel<<<(int)((wc_total + 255) / 256), 256>>>(W_ih, W_msg, T);
    fold_u_kernel<<<(T * H3 + 255) / 256, 256>>>(W_ih, W_msg, b_msg, T);

    const float* cur = hv0;
    for (int t = 0; t < T; t++) {
        zero_kernel<<<1024, 256>>>(pS, (size_t)N * H);
        scatter_kernel<<<(E * 8 + 63) / 64, 256>>>(cur, src, dst, E);
        xmat_kernel<<<(N * 64 + 255) / 256, 256>>>(cur, N);

        dim3 g1((N + 127) / 128, H3 / 128);
        mma_tf32x3_nt<<<g1, 256>>>(pX, pWc + (size_t)t * H3 * H2, pgi, N, H3, H2);
        mma_tf32x3_nt<<<g1, 256>>>(cur, W_hh + (size_t)t * H3 * H, pgh, N, H3, H);

        float* outp = (t == T - 1) ? (float*)d_out : ((t & 1) ? ph1 : ph0);
        gru_kernel<<<(N * H + 255) / 256, 256>>>(cur, b_ih + (size_t)t * H3, b_hh + (size_t)t * H3,
                                                 pu1 + (size_t)t * H3, pu2 + (size_t)t * H3,
                                                 outp, N);
        cur = outp;
    }
}